// round 2
// baseline (speedup 1.0000x reference)
#include <cuda_runtime.h>
#include <math.h>
#include <float.h>

// Problem constants
#define NQ_TOT   25216      // 197*128 query rows
#define NQ_CL    128        // class queries (t=0)
#define NQ_FT    25088      // feat queries  (t=1..196)
#define CDIM     768
#define KCB      4096       // codes per codebook
#define KTOT     8192
#define TOPK     3

// Output offsets (flattened tuple, all float32)
#define OFF_LOSS    0LL
#define OFF_QUANT   1LL
#define OFF_CLPERP  58097665LL
#define OFF_FTPERP  58097666LL
#define OFF_CLAVG   58097667LL
#define OFF_FTAVG   58101763LL
#define OFF_IDX     58105859LL
#define OFF_DIST    58181507LL   // NOTE: not 16B-aligned -> scalar access only!

// Scratch (device globals: no allocation allowed)
__device__ float  g_qnorm[NQ_TOT];
__device__ float  g_enorm[KTOT];         // [0..4095]=class, [4096..]=feat
__device__ int    g_idx[NQ_TOT * TOPK];  // raw (0..4095) index per selection
__device__ float  g_cnt[KTOT];           // class then feat counts
__device__ double g_loss[2];             // sum of squared diffs per codebook

// ---------------------------------------------------------------------------
__global__ void init_kernel() {
    int t = blockIdx.x * blockDim.x + threadIdx.x;
    if (t < KTOT) g_cnt[t] = 0.0f;
    if (t < 2) g_loss[t] = 0.0;
}

// ---------------------------------------------------------------------------
// Row L2-norms for queries (25216) and both codebooks (8192)
__global__ void norms_kernel(const float* __restrict__ feats,
                             const float* __restrict__ clsE,
                             const float* __restrict__ ftE) {
    int row = blockIdx.x;
    const float* src;
    float* dst;
    if (row < NQ_TOT)              { src = feats + (size_t)row * CDIM;            dst = g_qnorm + row; }
    else if (row < NQ_TOT + KCB)   { int r = row - NQ_TOT;       src = clsE + (size_t)r * CDIM; dst = g_enorm + r; }
    else                           { int r = row - NQ_TOT - KCB; src = ftE  + (size_t)r * CDIM; dst = g_enorm + KCB + r; }
    int t = threadIdx.x;  // 256
    float s = 0.f;
    #pragma unroll
    for (int i = t; i < CDIM; i += 256) { float v = src[i]; s += v * v; }
    __shared__ float red[256];
    red[t] = s; __syncthreads();
    for (int st = 128; st > 0; st >>= 1) { if (t < st) red[t] += red[t + st]; __syncthreads(); }
    if (t == 0) *dst = red[0];
}

// ---------------------------------------------------------------------------
// Fill the FLT_MAX padding half of the distance matrix (scalar, coalesced —
// the distance region base is only 4B-aligned).
__global__ void fill_kernel(float* __restrict__ out /* d_out */) {
    long long i = (long long)blockIdx.x * blockDim.x + threadIdx.x;
    const long long ntot = (long long)NQ_TOT * KCB;   // half of each row
    if (i >= ntot) return;
    int row = (int)(i >> 12);          // /4096
    int j   = (int)(i & 4095);
    int col = (row < NQ_CL) ? (KCB + j) : j;
    out[OFF_DIST + (long long)row * KTOT + col] = FLT_MAX;
}

// ---------------------------------------------------------------------------
// Tiled fp32 GEMM + distance epilogue.  128x128 tile, BK=8, 256 thr, 8x8/thread.
// All dims divide exactly (M in {128, 25088}, N=4096, K=768).
__global__ void __launch_bounds__(256)
gemm_dist(const float* __restrict__ Q, const float* __restrict__ E,
          const float* __restrict__ qn, const float* __restrict__ en,
          float* __restrict__ out, long long rowBase, int colOff) {
    __shared__ float As[8][128];
    __shared__ float Bs[8][128];
    int tid = threadIdx.x;
    int bm = blockIdx.x, bn = blockIdx.y;
    const float* Qb = Q + (size_t)bm * 128 * CDIM;
    const float* Eb = E + (size_t)bn * 128 * CDIM;
    int lr = tid >> 1;
    int lc = (tid & 1) * 4;
    int ty = tid >> 4, tx = tid & 15;
    float acc[8][8];
    #pragma unroll
    for (int i = 0; i < 8; i++)
        #pragma unroll
        for (int j = 0; j < 8; j++) acc[i][j] = 0.f;

    for (int k0 = 0; k0 < CDIM; k0 += 8) {
        float4 a = *(const float4*)(Qb + (size_t)lr * CDIM + k0 + lc);
        float4 b = *(const float4*)(Eb + (size_t)lr * CDIM + k0 + lc);
        As[lc + 0][lr] = a.x; As[lc + 1][lr] = a.y; As[lc + 2][lr] = a.z; As[lc + 3][lr] = a.w;
        Bs[lc + 0][lr] = b.x; Bs[lc + 1][lr] = b.y; Bs[lc + 2][lr] = b.z; Bs[lc + 3][lr] = b.w;
        __syncthreads();
        #pragma unroll
        for (int kk = 0; kk < 8; kk++) {
            float ar[8], br[8];
            #pragma unroll
            for (int i = 0; i < 8; i++) ar[i] = As[kk][ty * 8 + i];
            #pragma unroll
            for (int j = 0; j < 8; j++) br[j] = Bs[kk][tx * 8 + j];
            #pragma unroll
            for (int i = 0; i < 8; i++)
                #pragma unroll
                for (int j = 0; j < 8; j++) acc[i][j] += ar[i] * br[j];
        }
        __syncthreads();
    }
    #pragma unroll
    for (int i = 0; i < 8; i++) {
        int r = bm * 128 + ty * 8 + i;
        float qv = qn[r];
        #pragma unroll
        for (int j = 0; j < 8; j++) {
            int c = bn * 128 + tx * 8 + j;
            out[(rowBase + r) * (long long)KTOT + colOff + c] = qv + en[c] - 2.f * acc[i][j];
        }
    }
}

// ---------------------------------------------------------------------------
// Top-3 (smallest d, stable lower-index tie-break) per query row.
// Scalar loads (distance base only 4B-aligned), coalesced across threads.
__global__ void __launch_bounds__(128)
topk_kernel(const float* __restrict__ out /* d_out */, float* __restrict__ outIdx) {
    __shared__ float sd[KCB];
    __shared__ float rv[128];
    __shared__ int   ri[128];
    __shared__ int   winner;
    int q = blockIdx.x;
    int t = threadIdx.x;
    const float* row = out + OFF_DIST + (long long)q * KTOT + (q < NQ_CL ? 0 : KCB);
    for (int i = t; i < KCB; i += 128)
        sd[i] = row[i];
    __syncthreads();
    for (int sel = 0; sel < TOPK; sel++) {
        float bv = FLT_MAX; int bi = 0x3fffffff;
        int base = t * 32;
        #pragma unroll 8
        for (int i = base; i < base + 32; i++) {
            float v = sd[i];
            if (v < bv) { bv = v; bi = i; }
        }
        rv[t] = bv; ri[t] = bi; __syncthreads();
        for (int s = 64; s > 0; s >>= 1) {
            if (t < s) {
                float ov = rv[t + s]; int oi = ri[t + s];
                if (ov < rv[t] || (ov == rv[t] && oi < ri[t])) { rv[t] = ov; ri[t] = oi; }
            }
            __syncthreads();
        }
        if (t == 0) {
            winner = ri[0];
            int gi = q * TOPK + sel;
            g_idx[gi] = winner;
            outIdx[gi] = (float)(winner + (q < NQ_CL ? 0 : KCB));
            atomicAdd(&g_cnt[(q < NQ_CL ? 0 : KCB) + winner], 1.0f);
        }
        __syncthreads();
        if (t == 0) sd[winner] = FLT_MAX;
        __syncthreads();
    }
}

// ---------------------------------------------------------------------------
// Gather quantized = emb[idx] and accumulate commitment-loss sums.
__global__ void __launch_bounds__(256)
gather_loss(const float* __restrict__ feats,
            const float* __restrict__ clsE, const float* __restrict__ ftE,
            float* __restrict__ outQ /* d_out + OFF_QUANT */) {
    int g = blockIdx.x;          // 0..75647
    int q = g / TOPK;
    int idx = g_idx[g];
    const float* x = feats + (size_t)q * CDIM;
    const float* e = (q < NQ_CL ? clsE : ftE) + (size_t)idx * CDIM;
    int t = threadIdx.x;
    float s = 0.f;
    #pragma unroll
    for (int i = t; i < CDIM; i += 256) {
        float ev = e[i];
        float d = ev - x[i];
        outQ[(size_t)g * CDIM + i] = ev;
        s += d * d;
    }
    __shared__ float red[256];
    red[t] = s; __syncthreads();
    for (int st = 128; st > 0; st >>= 1) { if (t < st) red[t] += red[t + st]; __syncthreads(); }
    if (t == 0) atomicAdd(&g_loss[q < NQ_CL ? 0 : 1], (double)red[0]);
}

// ---------------------------------------------------------------------------
// avg_probs, perplexities, loss scalar.
__global__ void __launch_bounds__(1024)
finalize_kernel(float* __restrict__ out) {
    int b = blockIdx.x;          // 0=class, 1=feat
    int t = threadIdx.x;
    float N = (b == 0) ? (float)NQ_CL : (float)NQ_FT;
    float* avg = out + (b == 0 ? OFF_CLAVG : OFF_FTAVG);
    float ent = 0.f;
    for (int i = t; i < KCB; i += 1024) {
        float p = g_cnt[b * KCB + i] / N;
        avg[i] = p;
        ent += p * logf(p + 1e-10f);
    }
    __shared__ float red[1024];
    red[t] = ent; __syncthreads();
    for (int st = 512; st > 0; st >>= 1) { if (t < st) red[t] += red[t + st]; __syncthreads(); }
    if (t == 0) {
        out[b == 0 ? OFF_CLPERP : OFF_FTPERP] = expf(-red[0]);
        if (b == 0) {
            double mcl = g_loss[0] / ((double)NQ_CL * TOPK * CDIM);
            double mft = g_loss[1] / ((double)NQ_FT * TOPK * CDIM);
            out[OFF_LOSS] = (float)(0.25 * mft + 0.25 * mcl);
        }
    }
}

// ---------------------------------------------------------------------------
extern "C" void kernel_launch(void* const* d_in, const int* in_sizes, int n_in,
                              void* d_out, int out_size) {
    const float* feats = (const float*)d_in[0];   // (197,128,768)
    const float* clsE  = (const float*)d_in[1];   // (4096,768)
    const float* ftE   = (const float*)d_in[2];   // (4096,768)
    float* out = (float*)d_out;

    init_kernel<<<(KTOT + 255) / 256, 256>>>();
    norms_kernel<<<NQ_TOT + 2 * KCB, 256>>>(feats, clsE, ftE);

    {
        long long ntot = (long long)NQ_TOT * KCB;
        int blocks = (int)((ntot + 255) / 256);
        fill_kernel<<<blocks, 256>>>(out);
    }

    float* qnorm; cudaGetSymbolAddress((void**)&qnorm, g_qnorm);
    float* enorm; cudaGetSymbolAddress((void**)&enorm, g_enorm);

    // class: rows 0..127 -> dist cols [0,4096)
    gemm_dist<<<dim3(1, 32), 256>>>(feats, clsE, qnorm, enorm,
                                    out + OFF_DIST, 0LL, 0);
    // feat: rows 128..25215 -> dist cols [4096,8192)
    gemm_dist<<<dim3(196, 32), 256>>>(feats + (size_t)NQ_CL * CDIM, ftE,
                                      qnorm + NQ_CL, enorm + KCB,
                                      out + OFF_DIST, (long long)NQ_CL, KCB);

    topk_kernel<<<NQ_TOT, 128>>>(out, out + OFF_IDX);
    gather_loss<<<NQ_TOT * TOPK, 256>>>(feats, clsE, ftE, out + OFF_QUANT);
    finalize_kernel<<<2, 1024>>>(out);
}

// round 3
// speedup vs baseline: 1.0021x; 1.0021x over previous
#include <cuda_runtime.h>
#include <math.h>
#include <float.h>

// Problem constants
#define NQ_TOT   25216      // 197*128 query rows
#define NQ_CL    128        // class queries (t=0)
#define NQ_FT    25088      // feat queries  (t=1..196)
#define CDIM     768
#define KCB      4096       // codes per codebook
#define KTOT     8192
#define TOPK     3

// Output offsets (flattened tuple, all float32)
#define OFF_LOSS    0LL
#define OFF_QUANT   1LL
#define OFF_CLPERP  58097665LL
#define OFF_FTPERP  58097666LL
#define OFF_CLAVG   58097667LL
#define OFF_FTAVG   58101763LL
#define OFF_IDX     58105859LL
#define OFF_DIST    58181507LL   // NOTE: not 16B-aligned -> scalar access only!

// Scratch (device globals: no allocation allowed)
__device__ float  g_qnorm[NQ_TOT];
__device__ float  g_enorm[KTOT];         // [0..4095]=class, [4096..]=feat
__device__ int    g_idx[NQ_TOT * TOPK];  // raw (0..4095) index per selection
__device__ float  g_cnt[KTOT];           // class then feat counts
__device__ double g_loss[2];             // sum of squared diffs per codebook

// ---------------------------------------------------------------------------
__global__ void init_kernel() {
    int t = blockIdx.x * blockDim.x + threadIdx.x;
    if (t < KTOT) g_cnt[t] = 0.0f;
    if (t < 2) g_loss[t] = 0.0;
}

// ---------------------------------------------------------------------------
// Row L2-norms for queries (25216) and both codebooks (8192)
__global__ void norms_kernel(const float* __restrict__ feats,
                             const float* __restrict__ clsE,
                             const float* __restrict__ ftE) {
    int row = blockIdx.x;
    const float* src;
    float* dst;
    if (row < NQ_TOT)              { src = feats + (size_t)row * CDIM;            dst = g_qnorm + row; }
    else if (row < NQ_TOT + KCB)   { int r = row - NQ_TOT;       src = clsE + (size_t)r * CDIM; dst = g_enorm + r; }
    else                           { int r = row - NQ_TOT - KCB; src = ftE  + (size_t)r * CDIM; dst = g_enorm + KCB + r; }
    int t = threadIdx.x;  // 256
    float s = 0.f;
    #pragma unroll
    for (int i = t; i < CDIM; i += 256) { float v = src[i]; s += v * v; }
    __shared__ float red[256];
    red[t] = s; __syncthreads();
    for (int st = 128; st > 0; st >>= 1) { if (t < st) red[t] += red[t + st]; __syncthreads(); }
    if (t == 0) *dst = red[0];
}

// ---------------------------------------------------------------------------
// Fill the FLT_MAX padding half of the distance matrix (scalar, coalesced —
// the distance region base is only 4B-aligned).
__global__ void fill_kernel(float* __restrict__ out /* d_out */) {
    long long i = (long long)blockIdx.x * blockDim.x + threadIdx.x;
    const long long ntot = (long long)NQ_TOT * KCB;   // half of each row
    if (i >= ntot) return;
    int row = (int)(i >> 12);          // /4096
    int j   = (int)(i & 4095);
    int col = (row < NQ_CL) ? (KCB + j) : j;
    out[OFF_DIST + (long long)row * KTOT + col] = FLT_MAX;
}

// ---------------------------------------------------------------------------
// Tiled fp32 GEMM + distance epilogue.  128x128 tile, BK=8, 256 thr, 8x8/thread.
// All dims divide exactly (M in {128, 25088}, N=4096, K=768).
__global__ void __launch_bounds__(256)
gemm_dist(const float* __restrict__ Q, const float* __restrict__ E,
          const float* __restrict__ qn, const float* __restrict__ en,
          float* __restrict__ out, long long rowBase, int colOff) {
    __shared__ float As[8][128];
    __shared__ float Bs[8][128];
    int tid = threadIdx.x;
    int bm = blockIdx.x, bn = blockIdx.y;
    const float* Qb = Q + (size_t)bm * 128 * CDIM;
    const float* Eb = E + (size_t)bn * 128 * CDIM;
    int lr = tid >> 1;
    int lc = (tid & 1) * 4;
    int ty = tid >> 4, tx = tid & 15;
    float acc[8][8];
    #pragma unroll
    for (int i = 0; i < 8; i++)
        #pragma unroll
        for (int j = 0; j < 8; j++) acc[i][j] = 0.f;

    for (int k0 = 0; k0 < CDIM; k0 += 8) {
        float4 a = *(const float4*)(Qb + (size_t)lr * CDIM + k0 + lc);
        float4 b = *(const float4*)(Eb + (size_t)lr * CDIM + k0 + lc);
        As[lc + 0][lr] = a.x; As[lc + 1][lr] = a.y; As[lc + 2][lr] = a.z; As[lc + 3][lr] = a.w;
        Bs[lc + 0][lr] = b.x; Bs[lc + 1][lr] = b.y; Bs[lc + 2][lr] = b.z; Bs[lc + 3][lr] = b.w;
        __syncthreads();
        #pragma unroll
        for (int kk = 0; kk < 8; kk++) {
            float ar[8], br[8];
            #pragma unroll
            for (int i = 0; i < 8; i++) ar[i] = As[kk][ty * 8 + i];
            #pragma unroll
            for (int j = 0; j < 8; j++) br[j] = Bs[kk][tx * 8 + j];
            #pragma unroll
            for (int i = 0; i < 8; i++)
                #pragma unroll
                for (int j = 0; j < 8; j++) acc[i][j] += ar[i] * br[j];
        }
        __syncthreads();
    }
    #pragma unroll
    for (int i = 0; i < 8; i++) {
        int r = bm * 128 + ty * 8 + i;
        float qv = qn[r];
        #pragma unroll
        for (int j = 0; j < 8; j++) {
            int c = bn * 128 + tx * 8 + j;
            out[(rowBase + r) * (long long)KTOT + colOff + c] = qv + en[c] - 2.f * acc[i][j];
        }
    }
}

// ---------------------------------------------------------------------------
// Top-3 (smallest d, stable lower-index tie-break) per query row.
// Scalar loads (distance base only 4B-aligned), coalesced across threads.
__global__ void __launch_bounds__(128)
topk_kernel(const float* __restrict__ out /* d_out */, float* __restrict__ outIdx) {
    __shared__ float sd[KCB];
    __shared__ float rv[128];
    __shared__ int   ri[128];
    __shared__ int   winner;
    int q = blockIdx.x;
    int t = threadIdx.x;
    const float* row = out + OFF_DIST + (long long)q * KTOT + (q < NQ_CL ? 0 : KCB);
    for (int i = t; i < KCB; i += 128)
        sd[i] = row[i];
    __syncthreads();
    for (int sel = 0; sel < TOPK; sel++) {
        float bv = FLT_MAX; int bi = 0x3fffffff;
        int base = t * 32;
        #pragma unroll 8
        for (int i = base; i < base + 32; i++) {
            float v = sd[i];
            if (v < bv) { bv = v; bi = i; }
        }
        rv[t] = bv; ri[t] = bi; __syncthreads();
        for (int s = 64; s > 0; s >>= 1) {
            if (t < s) {
                float ov = rv[t + s]; int oi = ri[t + s];
                if (ov < rv[t] || (ov == rv[t] && oi < ri[t])) { rv[t] = ov; ri[t] = oi; }
            }
            __syncthreads();
        }
        if (t == 0) {
            winner = ri[0];
            int gi = q * TOPK + sel;
            g_idx[gi] = winner;
            outIdx[gi] = (float)(winner + (q < NQ_CL ? 0 : KCB));
            atomicAdd(&g_cnt[(q < NQ_CL ? 0 : KCB) + winner], 1.0f);
        }
        __syncthreads();
        if (t == 0) sd[winner] = FLT_MAX;
        __syncthreads();
    }
}

// ---------------------------------------------------------------------------
// Gather quantized = emb[idx] and accumulate commitment-loss sums.
__global__ void __launch_bounds__(256)
gather_loss(const float* __restrict__ feats,
            const float* __restrict__ clsE, const float* __restrict__ ftE,
            float* __restrict__ outQ /* d_out + OFF_QUANT */) {
    int g = blockIdx.x;          // 0..75647
    int q = g / TOPK;
    int idx = g_idx[g];
    const float* x = feats + (size_t)q * CDIM;
    const float* e = (q < NQ_CL ? clsE : ftE) + (size_t)idx * CDIM;
    int t = threadIdx.x;
    float s = 0.f;
    #pragma unroll
    for (int i = t; i < CDIM; i += 256) {
        float ev = e[i];
        float d = ev - x[i];
        outQ[(size_t)g * CDIM + i] = ev;
        s += d * d;
    }
    __shared__ float red[256];
    red[t] = s; __syncthreads();
    for (int st = 128; st > 0; st >>= 1) { if (t < st) red[t] += red[t + st]; __syncthreads(); }
    if (t == 0) atomicAdd(&g_loss[q < NQ_CL ? 0 : 1], (double)red[0]);
}

// ---------------------------------------------------------------------------
// avg_probs, perplexities, loss scalar.
__global__ void __launch_bounds__(1024)
finalize_kernel(float* __restrict__ out) {
    int b = blockIdx.x;          // 0=class, 1=feat
    int t = threadIdx.x;
    float N = (b == 0) ? (float)NQ_CL : (float)NQ_FT;
    float* avg = out + (b == 0 ? OFF_CLAVG : OFF_FTAVG);
    float ent = 0.f;
    for (int i = t; i < KCB; i += 1024) {
        float p = g_cnt[b * KCB + i] / N;
        avg[i] = p;
        ent += p * logf(p + 1e-10f);
    }
    __shared__ float red[1024];
    red[t] = ent; __syncthreads();
    for (int st = 512; st > 0; st >>= 1) { if (t < st) red[t] += red[t + st]; __syncthreads(); }
    if (t == 0) {
        out[b == 0 ? OFF_CLPERP : OFF_FTPERP] = expf(-red[0]);
        if (b == 0) {
            double mcl = g_loss[0] / ((double)NQ_CL * TOPK * CDIM);
            double mft = g_loss[1] / ((double)NQ_FT * TOPK * CDIM);
            out[OFF_LOSS] = (float)(0.25 * mft + 0.25 * mcl);
        }
    }
}

// ---------------------------------------------------------------------------
extern "C" void kernel_launch(void* const* d_in, const int* in_sizes, int n_in,
                              void* d_out, int out_size) {
    const float* feats = (const float*)d_in[0];   // (197,128,768)
    const float* clsE  = (const float*)d_in[1];   // (4096,768)
    const float* ftE   = (const float*)d_in[2];   // (4096,768)
    float* out = (float*)d_out;

    init_kernel<<<(KTOT + 255) / 256, 256>>>();
    norms_kernel<<<NQ_TOT + 2 * KCB, 256>>>(feats, clsE, ftE);

    {
        long long ntot = (long long)NQ_TOT * KCB;
        int blocks = (int)((ntot + 255) / 256);
        fill_kernel<<<blocks, 256>>>(out);
    }

    float* qnorm; cudaGetSymbolAddress((void**)&qnorm, g_qnorm);
    float* enorm; cudaGetSymbolAddress((void**)&enorm, g_enorm);

    // class: rows 0..127 -> dist cols [0,4096)
    gemm_dist<<<dim3(1, 32), 256>>>(feats, clsE, qnorm, enorm,
                                    out + OFF_DIST, 0LL, 0);
    // feat: rows 128..25215 -> dist cols [4096,8192)
    gemm_dist<<<dim3(196, 32), 256>>>(feats + (size_t)NQ_CL * CDIM, ftE,
                                      qnorm + NQ_CL, enorm + KCB,
                                      out + OFF_DIST, (long long)NQ_CL, KCB);

    topk_kernel<<<NQ_TOT, 128>>>(out, out + OFF_IDX);
    gather_loss<<<NQ_TOT * TOPK, 256>>>(feats, clsE, ftE, out + OFF_QUANT);
    finalize_kernel<<<2, 1024>>>(out);
}

// round 10
// speedup vs baseline: 1.3290x; 1.3262x over previous
#include <cuda_runtime.h>
#include <cuda_bf16.h>
#include <mma.h>
#include <math.h>
#include <float.h>
#include <stdint.h>

using namespace nvcuda;

// Problem constants
#define NQ_TOT   25216
#define NQ_CL    128
#define NQ_FT    25088
#define CDIM     768
#define KCB      4096
#define KTOT     8192
#define TOPK     3
#define NCAND    16

// Output offsets (flattened tuple, all float32)
#define OFF_LOSS    0LL
#define OFF_QUANT   1LL
#define OFF_CLPERP  58097665LL
#define OFF_FTPERP  58097666LL
#define OFF_CLAVG   58097667LL
#define OFF_FTAVG   58101763LL
#define OFF_IDX     58105859LL
#define OFF_DIST    58181507LL   // not 16B-aligned: scalar access only in dist region

// ---------------------------------------------------------------------------
// Scratch (device globals — no allocation allowed)
__device__ __nv_bfloat16 g_qbf[(size_t)NQ_TOT * CDIM];
__device__ __nv_bfloat16 g_cbf[(size_t)KCB * CDIM];
__device__ __nv_bfloat16 g_fbf[(size_t)KCB * CDIM];
__device__ float  g_qnorm[NQ_TOT];
__device__ float  g_enorm[KTOT];          // [0..4095]=class, [4096..]=feat
__device__ int    g_cand[NQ_TOT * NCAND]; // approx top-16 raw indices
__device__ float  g_rd[NQ_TOT * NCAND];   // exact fp32 rescored distances
__device__ int    g_idx[NQ_TOT * TOPK];   // exact top-3 raw indices
__device__ float  g_cnt[KTOT];
__device__ double g_loss[2];

// ---------------------------------------------------------------------------
__global__ void init_kernel() {
    int t = blockIdx.x * blockDim.x + threadIdx.x;
    if (t < KTOT) g_cnt[t] = 0.0f;
    if (t < 2) g_loss[t] = 0.0;
}

// Fused: fp32 -> bf16 conversion AND row L2-norms (one read pass).
// Norm arithmetic is bit-identical to the R3 kernel that matched jax:
// strided fmaf accumulation + shared tree reduction.
__global__ void conv_norms_kernel(const float* __restrict__ feats,
                                  const float* __restrict__ clsE,
                                  const float* __restrict__ ftE) {
    int row = blockIdx.x;
    const float* src; float* ndst; __nv_bfloat16* bdst;
    if (row < NQ_TOT) {
        src = feats + (size_t)row * CDIM; ndst = g_qnorm + row; bdst = g_qbf + (size_t)row * CDIM;
    } else if (row < NQ_TOT + KCB) {
        int r = row - NQ_TOT;
        src = clsE + (size_t)r * CDIM; ndst = g_enorm + r; bdst = g_cbf + (size_t)r * CDIM;
    } else {
        int r = row - NQ_TOT - KCB;
        src = ftE + (size_t)r * CDIM; ndst = g_enorm + KCB + r; bdst = g_fbf + (size_t)r * CDIM;
    }
    int t = threadIdx.x;  // 256
    float s = 0.f;
    #pragma unroll
    for (int i = t; i < CDIM; i += 256) {
        float v = src[i];
        bdst[i] = __float2bfloat16(v);
        s = fmaf(v, v, s);
    }
    __shared__ float red[256];
    red[t] = s; __syncthreads();
    for (int st = 128; st > 0; st >>= 1) { if (t < st) red[t] += red[t + st]; __syncthreads(); }
    if (t == 0) *ndst = red[0];
}

// FLT_MAX padding half of the distance matrix (scalar, coalesced)
__global__ void fill_kernel(float* __restrict__ out) {
    long long i = (long long)blockIdx.x * blockDim.x + threadIdx.x;
    const long long ntot = (long long)NQ_TOT * KCB;
    if (i >= ntot) return;
    int row = (int)(i >> 12);
    int j   = (int)(i & 4095);
    int col = (row < NQ_CL) ? (KCB + j) : j;
    out[OFF_DIST + (long long)row * KTOT + col] = FLT_MAX;
}

// ---------------------------------------------------------------------------
// bf16 WMMA GEMM + distance epilogue.
// CTA tile 128x128, 8 warps (2 n-groups x 4 m-groups), warp tile 32x64.
// BK=64, double-buffered smem (ld=80 bf16 keeps 16B-aligned uint4 stores).
#define BK    64
#define LDS_  80     // row stride in bf16 elements (160B rows, 16B aligned)
#define NCHK  (CDIM / BK)   // 12

__global__ void __launch_bounds__(256, 1)
gemm_wmma(const __nv_bfloat16* __restrict__ A,   // [M, 768] queries (bf16)
          const __nv_bfloat16* __restrict__ B,   // [4096, 768] codebook (bf16)
          const float* __restrict__ qn, const float* __restrict__ en,
          float* __restrict__ dist, long long rowBase, int colOff)
{
    extern __shared__ char smem[];
    const int tid = threadIdx.x;
    const int wid = tid >> 5;
    const int bm = blockIdx.x, bn = blockIdx.y;
    const int wm = wid & 3;     // 0..3 -> 32-row group
    const int wn = wid >> 2;    // 0..1 -> 64-col group

    __nv_bfloat16* sA[2] = { (__nv_bfloat16*)smem,
                             (__nv_bfloat16*)(smem + 40960) };
    __nv_bfloat16* sB[2] = { (__nv_bfloat16*)(smem + 20480),
                             (__nv_bfloat16*)(smem + 61440) };

    const __nv_bfloat16* Abase = A + (size_t)bm * 128 * CDIM;
    const __nv_bfloat16* Bbase = B + (size_t)bn * 128 * CDIM;

    wmma::fragment<wmma::accumulator, 16, 16, 16, float> acc[2][4];
    #pragma unroll
    for (int i = 0; i < 2; i++)
        #pragma unroll
        for (int j = 0; j < 4; j++) wmma::fill_fragment(acc[i][j], 0.0f);

    uint4 ra[4], rb[4];
    #pragma unroll
    for (int v = 0; v < 4; v++) {
        int u = tid + v * 256;
        int row = u >> 3, c8 = u & 7;
        ra[v] = *(const uint4*)(Abase + (size_t)row * CDIM + c8 * 8);
        rb[v] = *(const uint4*)(Bbase + (size_t)row * CDIM + c8 * 8);
    }
    #pragma unroll
    for (int v = 0; v < 4; v++) {
        int u = tid + v * 256;
        int row = u >> 3, c8 = u & 7;
        *(uint4*)(sA[0] + row * LDS_ + c8 * 8) = ra[v];
        *(uint4*)(sB[0] + row * LDS_ + c8 * 8) = rb[v];
    }
    __syncthreads();

    for (int c = 0; c < NCHK; c++) {
        const int s = c & 1;
        if (c + 1 < NCHK) {
            const int kk = (c + 1) * BK;
            #pragma unroll
            for (int v = 0; v < 4; v++) {
                int u = tid + v * 256;
                int row = u >> 3, c8 = u & 7;
                ra[v] = *(const uint4*)(Abase + (size_t)row * CDIM + kk + c8 * 8);
                rb[v] = *(const uint4*)(Bbase + (size_t)row * CDIM + kk + c8 * 8);
            }
        }

        #pragma unroll
        for (int kk = 0; kk < BK / 16; kk++) {
            wmma::fragment<wmma::matrix_a, 16, 16, 16, __nv_bfloat16, wmma::row_major> af[2];
            wmma::fragment<wmma::matrix_b, 16, 16, 16, __nv_bfloat16, wmma::col_major> bf[4];
            #pragma unroll
            for (int i = 0; i < 2; i++)
                wmma::load_matrix_sync(af[i], sA[s] + (wm * 32 + i * 16) * LDS_ + kk * 16, LDS_);
            #pragma unroll
            for (int j = 0; j < 4; j++)
                wmma::load_matrix_sync(bf[j], sB[s] + (wn * 64 + j * 16) * LDS_ + kk * 16, LDS_);
            #pragma unroll
            for (int i = 0; i < 2; i++)
                #pragma unroll
                for (int j = 0; j < 4; j++)
                    wmma::mma_sync(acc[i][j], af[i], bf[j], acc[i][j]);
        }

        if (c + 1 < NCHK) {
            const int ns = (c + 1) & 1;
            #pragma unroll
            for (int v = 0; v < 4; v++) {
                int u = tid + v * 256;
                int row = u >> 3, c8 = u & 7;
                *(uint4*)(sA[ns] + row * LDS_ + c8 * 8) = ra[v];
                *(uint4*)(sB[ns] + row * LDS_ + c8 * 8) = rb[v];
            }
        }
        __syncthreads();
    }

    // Epilogue: acc -> smem (f32, ld=132) -> coalesced scalar global stores
    float* sf = (float*)smem;
    #pragma unroll
    for (int i = 0; i < 2; i++)
        #pragma unroll
        for (int j = 0; j < 4; j++)
            wmma::store_matrix_sync(sf + (size_t)(wm * 32 + i * 16) * 132 + wn * 64 + j * 16,
                                    acc[i][j], 132, wmma::mem_row_major);
    __syncthreads();

    const int colL = tid & 127;
    const int r0   = tid >> 7;
    const int colG = bn * 128 + colL;
    const float env = en[colG];
    const long long cbase = (long long)colOff + colG;
    #pragma unroll 4
    for (int r = r0; r < 128; r += 2) {
        int rg = bm * 128 + r;
        dist[(rowBase + rg) * (long long)KTOT + cbase] =
            qn[rg] + env - 2.0f * sf[(size_t)r * 132 + colL];
    }
}

// ---------------------------------------------------------------------------
// Approximate top-16 per query row (stable lower-index tie-break)
__global__ void __launch_bounds__(128)
topk_kernel(const float* __restrict__ out) {
    __shared__ float sd[KCB];
    __shared__ float rv[128];
    __shared__ int   ri[128];
    __shared__ int   winner;
    int q = blockIdx.x;
    int t = threadIdx.x;
    const float* row = out + OFF_DIST + (long long)q * KTOT + (q < NQ_CL ? 0 : KCB);
    for (int i = t; i < KCB; i += 128) sd[i] = row[i];
    __syncthreads();
    for (int sel = 0; sel < NCAND; sel++) {
        float bv = FLT_MAX; int bi = 0x3fffffff;
        int base = t * 32;
        #pragma unroll 8
        for (int i = base; i < base + 32; i++) {
            float v = sd[i];
            if (v < bv) { bv = v; bi = i; }
        }
        rv[t] = bv; ri[t] = bi; __syncthreads();
        for (int s = 64; s > 0; s >>= 1) {
            if (t < s) {
                float ov = rv[t + s]; int oi = ri[t + s];
                if (ov < rv[t] || (ov == rv[t] && oi < ri[t])) { rv[t] = ov; ri[t] = oi; }
            }
            __syncthreads();
        }
        if (t == 0) { winner = ri[0]; g_cand[q * NCAND + sel] = winner; }
        __syncthreads();
        if (t == 0) sd[winner] = FLT_MAX;
        __syncthreads();
    }
}

// ---------------------------------------------------------------------------
// Exact fp32 rescore: one thread per (query, candidate), SEQUENTIAL fmaf over
// k = 0..767 in index order — bit-identical rounding to the R3 fp32 GEMM whose
// selection matched jax exactly. Epilogue: (qn + en) - 2.f * acc (same expr).
__global__ void __launch_bounds__(256)
rescore_pairs(const float* __restrict__ feats,
              const float* __restrict__ clsE, const float* __restrict__ ftE) {
    int g = blockIdx.x * 256 + threadIdx.x;
    if (g >= NQ_TOT * NCAND) return;
    int q = g / NCAND;
    int cand = g_cand[g];
    const float4* x = (const float4*)(feats + (size_t)q * CDIM);
    const float4* e = (const float4*)((q < NQ_CL ? clsE : ftE) + (size_t)cand * CDIM);
    float s = 0.f;
    #pragma unroll 8
    for (int i = 0; i < CDIM / 4; i++) {
        float4 a = x[i], b = e[i];
        s = fmaf(a.x, b.x, s);
        s = fmaf(a.y, b.y, s);
        s = fmaf(a.z, b.z, s);
        s = fmaf(a.w, b.w, s);
    }
    g_rd[g] = (g_qnorm[q] + g_enorm[(q < NQ_CL ? 0 : KCB) + cand]) - 2.f * s;
}

// Final top-3 from exact distances, lower-index tie-break; counts + idx output
__global__ void __launch_bounds__(256)
select_kernel(float* __restrict__ out) {
    int q = blockIdx.x * 256 + threadIdx.x;
    if (q >= NQ_TOT) return;
    float d[NCAND]; int id[NCAND]; bool used[NCAND];
    #pragma unroll
    for (int c = 0; c < NCAND; c++) {
        d[c] = g_rd[q * NCAND + c];
        id[c] = g_cand[q * NCAND + c];
        used[c] = false;
    }
    int base = (q < NQ_CL ? 0 : KCB);
    for (int sel = 0; sel < TOPK; sel++) {
        float bv = FLT_MAX; int bi = 0x7fffffff; int bw = 0;
        #pragma unroll
        for (int c = 0; c < NCAND; c++) {
            if (used[c]) continue;
            if (d[c] < bv || (d[c] == bv && id[c] < bi)) { bv = d[c]; bi = id[c]; bw = c; }
        }
        used[bw] = true;
        g_idx[q * TOPK + sel] = bi;
        out[OFF_IDX + q * TOPK + sel] = (float)(bi + base);
        atomicAdd(&g_cnt[base + bi], 1.0f);
    }
}

// Gather quantized = emb[idx] and accumulate commitment-loss sums
__global__ void __launch_bounds__(256)
gather_loss(const float* __restrict__ feats,
            const float* __restrict__ clsE, const float* __restrict__ ftE,
            float* __restrict__ outQ) {
    int g = blockIdx.x;
    int q = g / TOPK;
    int idx = g_idx[g];
    const float* x = feats + (size_t)q * CDIM;
    const float* e = (q < NQ_CL ? clsE : ftE) + (size_t)idx * CDIM;
    int t = threadIdx.x;
    float s = 0.f;
    #pragma unroll
    for (int i = t; i < CDIM; i += 256) {
        float ev = e[i];
        float d = ev - x[i];
        outQ[(size_t)g * CDIM + i] = ev;
        s += d * d;
    }
    __shared__ float red[256];
    red[t] = s; __syncthreads();
    for (int st = 128; st > 0; st >>= 1) { if (t < st) red[t] += red[t + st]; __syncthreads(); }
    if (t == 0) atomicAdd(&g_loss[q < NQ_CL ? 0 : 1], (double)red[0]);
}

// avg_probs, perplexities, loss scalar
__global__ void __launch_bounds__(1024)
finalize_kernel(float* __restrict__ out) {
    int b = blockIdx.x;
    int t = threadIdx.x;
    float N = (b == 0) ? (float)NQ_CL : (float)NQ_FT;
    float* avg = out + (b == 0 ? OFF_CLAVG : OFF_FTAVG);
    float ent = 0.f;
    for (int i = t; i < KCB; i += 1024) {
        float p = g_cnt[b * KCB + i] / N;
        avg[i] = p;
        ent += p * logf(p + 1e-10f);
    }
    __shared__ float red[1024];
    red[t] = ent; __syncthreads();
    for (int st = 512; st > 0; st >>= 1) { if (t < st) red[t] += red[t + st]; __syncthreads(); }
    if (t == 0) {
        out[b == 0 ? OFF_CLPERP : OFF_FTPERP] = expf(-red[0]);
        if (b == 0) {
            double mcl = g_loss[0] / ((double)NQ_CL * TOPK * CDIM);
            double mft = g_loss[1] / ((double)NQ_FT * TOPK * CDIM);
            out[OFF_LOSS] = (float)(0.25 * mft + 0.25 * mcl);
        }
    }
}

// ---------------------------------------------------------------------------
extern "C" void kernel_launch(void* const* d_in, const int* in_sizes, int n_in,
                              void* d_out, int out_size) {
    const float* feats = (const float*)d_in[0];   // (197,128,768)
    const float* clsE  = (const float*)d_in[1];   // (4096,768)
    const float* ftE   = (const float*)d_in[2];   // (4096,768)
    float* out = (float*)d_out;

    const int SMEM_GEMM = 81920;   // max(2*40960 staging, 67584 epilogue)
    cudaFuncSetAttribute(gemm_wmma, cudaFuncAttributeMaxDynamicSharedMemorySize, SMEM_GEMM);

    init_kernel<<<(KTOT + 255) / 256, 256>>>();
    conv_norms_kernel<<<NQ_TOT + 2 * KCB, 256>>>(feats, clsE, ftE);

    {
        long long ntot = (long long)NQ_TOT * KCB;
        fill_kernel<<<(int)((ntot + 255) / 256), 256>>>(out);
    }

    __nv_bfloat16 *qbf, *cbf, *fbf;
    float *qnorm, *enorm;
    cudaGetSymbolAddress((void**)&qbf, g_qbf);
    cudaGetSymbolAddress((void**)&cbf, g_cbf);
    cudaGetSymbolAddress((void**)&fbf, g_fbf);
    cudaGetSymbolAddress((void**)&qnorm, g_qnorm);
    cudaGetSymbolAddress((void**)&enorm, g_enorm);

    // class: rows 0..127 -> dist cols [0,4096)
    gemm_wmma<<<dim3(1, 32), 256, SMEM_GEMM>>>(
        qbf, cbf, qnorm, enorm, out + OFF_DIST, 0LL, 0);
    // feat: rows 128..25215 -> dist cols [4096,8192)  (25088 = 196*128 exactly)
    gemm_wmma<<<dim3(196, 32), 256, SMEM_GEMM>>>(
        qbf + (size_t)NQ_CL * CDIM, fbf, qnorm + NQ_CL, enorm + KCB,
        out + OFF_DIST, (long long)NQ_CL, KCB);

    topk_kernel<<<NQ_TOT, 128>>>(out);
    rescore_pairs<<<(NQ_TOT * NCAND + 255) / 256, 256>>>(feats, clsE, ftE);
    select_kernel<<<(NQ_TOT + 255) / 256, 256>>>(out);
    gather_loss<<<NQ_TOT * TOPK, 256>>>(feats, clsE, ftE, out + OFF_QUANT);
    finalize_kernel<<<2, 1024>>>(out);
}

// round 11
// speedup vs baseline: 2.5755x; 1.9379x over previous
#include <cuda_runtime.h>
#include <cuda_bf16.h>
#include <mma.h>
#include <math.h>
#include <float.h>
#include <stdint.h>

using namespace nvcuda;

// Problem constants
#define NQ_TOT   25216
#define NQ_CL    128
#define NQ_FT    25088
#define CDIM     768
#define KCB      4096
#define KTOT     8192
#define TOPK     3
#define NCAND    16

// Output offsets (flattened tuple, all float32)
#define OFF_LOSS    0LL
#define OFF_QUANT   1LL
#define OFF_CLPERP  58097665LL
#define OFF_FTPERP  58097666LL
#define OFF_CLAVG   58097667LL
#define OFF_FTAVG   58101763LL
#define OFF_IDX     58105859LL
#define OFF_DIST    58181507LL   // not 16B-aligned: scalar access only in dist region

// ---------------------------------------------------------------------------
// Scratch (device globals — no allocation allowed)
__device__ __nv_bfloat16 g_qbf[(size_t)NQ_TOT * CDIM];
__device__ __nv_bfloat16 g_cbf[(size_t)KCB * CDIM];
__device__ __nv_bfloat16 g_fbf[(size_t)KCB * CDIM];
__device__ float  g_qnorm[NQ_TOT];
__device__ float  g_enorm[KTOT];          // [0..4095]=class, [4096..]=feat
__device__ int    g_cand[NQ_TOT * NCAND]; // approx top-16 raw indices
__device__ float  g_rd[NQ_TOT * NCAND];   // exact fp32 rescored distances
__device__ int    g_idx[NQ_TOT * TOPK];   // exact top-3 raw indices
__device__ float  g_cnt[KTOT];
__device__ double g_loss[2];

// ---------------------------------------------------------------------------
__global__ void init_kernel() {
    int t = blockIdx.x * blockDim.x + threadIdx.x;
    if (t < KTOT) g_cnt[t] = 0.0f;
    if (t < 2) g_loss[t] = 0.0;
}

// Fused: fp32 -> bf16 conversion AND row L2-norms (one read pass).
__global__ void conv_norms_kernel(const float* __restrict__ feats,
                                  const float* __restrict__ clsE,
                                  const float* __restrict__ ftE) {
    int row = blockIdx.x;
    const float* src; float* ndst; __nv_bfloat16* bdst;
    if (row < NQ_TOT) {
        src = feats + (size_t)row * CDIM; ndst = g_qnorm + row; bdst = g_qbf + (size_t)row * CDIM;
    } else if (row < NQ_TOT + KCB) {
        int r = row - NQ_TOT;
        src = clsE + (size_t)r * CDIM; ndst = g_enorm + r; bdst = g_cbf + (size_t)r * CDIM;
    } else {
        int r = row - NQ_TOT - KCB;
        src = ftE + (size_t)r * CDIM; ndst = g_enorm + KCB + r; bdst = g_fbf + (size_t)r * CDIM;
    }
    int t = threadIdx.x;  // 256
    float s = 0.f;
    #pragma unroll
    for (int i = t; i < CDIM; i += 256) {
        float v = src[i];
        bdst[i] = __float2bfloat16(v);
        s = fmaf(v, v, s);
    }
    __shared__ float red[256];
    red[t] = s; __syncthreads();
    for (int st = 128; st > 0; st >>= 1) { if (t < st) red[t] += red[t + st]; __syncthreads(); }
    if (t == 0) *ndst = red[0];
}

// FLT_MAX padding half of the distance matrix (scalar, coalesced)
__global__ void fill_kernel(float* __restrict__ out) {
    long long i = (long long)blockIdx.x * blockDim.x + threadIdx.x;
    const long long ntot = (long long)NQ_TOT * KCB;
    if (i >= ntot) return;
    int row = (int)(i >> 12);
    int j   = (int)(i & 4095);
    int col = (row < NQ_CL) ? (KCB + j) : j;
    out[OFF_DIST + (long long)row * KTOT + col] = FLT_MAX;
}

// ---------------------------------------------------------------------------
// bf16 WMMA GEMM + distance epilogue.
// CTA tile 128x128, 4 warps in a 2x2 grid, 64x64 warp tile (4x4 frags).
// BK=32, double-buffered smem, 2 CTAs/SM.
#define BK    32
#define LDS_  40     // bf16 row stride (80B, 16B-aligned)
#define NCHK  (CDIM / BK)   // 24

__global__ void __launch_bounds__(128, 2)
gemm_wmma(const __nv_bfloat16* __restrict__ A,   // [M, 768] queries (bf16)
          const __nv_bfloat16* __restrict__ B,   // [4096, 768] codebook (bf16)
          const float* __restrict__ qn, const float* __restrict__ en,
          float* __restrict__ dist, long long rowBase, int colOff)
{
    extern __shared__ char smem[];
    const int tid = threadIdx.x;
    const int wid = tid >> 5;
    const int bm = blockIdx.x, bn = blockIdx.y;
    const int wm = wid & 1;     // 2 row groups of 64
    const int wn = wid >> 1;    // 2 col groups of 64

    // per stage: A 128*40*2 = 10240 B, B same -> 20480 B; 2 stages = 40960 B
    __nv_bfloat16* sA[2] = { (__nv_bfloat16*)smem,
                             (__nv_bfloat16*)(smem + 20480) };
    __nv_bfloat16* sB[2] = { (__nv_bfloat16*)(smem + 10240),
                             (__nv_bfloat16*)(smem + 30720) };

    const __nv_bfloat16* Abase = A + (size_t)bm * 128 * CDIM;
    const __nv_bfloat16* Bbase = B + (size_t)bn * 128 * CDIM;

    wmma::fragment<wmma::accumulator, 16, 16, 16, float> acc[4][4];
    #pragma unroll
    for (int i = 0; i < 4; i++)
        #pragma unroll
        for (int j = 0; j < 4; j++) wmma::fill_fragment(acc[i][j], 0.0f);

    // per chunk: each matrix is 128 rows x 32 cols bf16 = 512 uint4;
    // 128 threads x 4 uint4: u = tid + v*128, row = u>>2, c8 = u&3
    uint4 ra[4], rb[4];
    #pragma unroll
    for (int v = 0; v < 4; v++) {
        int u = tid + v * 128;
        int row = u >> 2, c8 = u & 3;
        ra[v] = *(const uint4*)(Abase + (size_t)row * CDIM + c8 * 8);
        rb[v] = *(const uint4*)(Bbase + (size_t)row * CDIM + c8 * 8);
    }
    #pragma unroll
    for (int v = 0; v < 4; v++) {
        int u = tid + v * 128;
        int row = u >> 2, c8 = u & 3;
        *(uint4*)(sA[0] + row * LDS_ + c8 * 8) = ra[v];
        *(uint4*)(sB[0] + row * LDS_ + c8 * 8) = rb[v];
    }
    __syncthreads();

    for (int c = 0; c < NCHK; c++) {
        const int s = c & 1;
        if (c + 1 < NCHK) {
            const int kk = (c + 1) * BK;
            #pragma unroll
            for (int v = 0; v < 4; v++) {
                int u = tid + v * 128;
                int row = u >> 2, c8 = u & 3;
                ra[v] = *(const uint4*)(Abase + (size_t)row * CDIM + kk + c8 * 8);
                rb[v] = *(const uint4*)(Bbase + (size_t)row * CDIM + kk + c8 * 8);
            }
        }

        #pragma unroll
        for (int kk = 0; kk < BK / 16; kk++) {
            wmma::fragment<wmma::matrix_a, 16, 16, 16, __nv_bfloat16, wmma::row_major> af[4];
            wmma::fragment<wmma::matrix_b, 16, 16, 16, __nv_bfloat16, wmma::col_major> bf[4];
            #pragma unroll
            for (int i = 0; i < 4; i++)
                wmma::load_matrix_sync(af[i], sA[s] + (wm * 64 + i * 16) * LDS_ + kk * 16, LDS_);
            #pragma unroll
            for (int j = 0; j < 4; j++)
                wmma::load_matrix_sync(bf[j], sB[s] + (wn * 64 + j * 16) * LDS_ + kk * 16, LDS_);
            #pragma unroll
            for (int i = 0; i < 4; i++)
                #pragma unroll
                for (int j = 0; j < 4; j++)
                    wmma::mma_sync(acc[i][j], af[i], bf[j], acc[i][j]);
        }

        if (c + 1 < NCHK) {
            const int ns = (c + 1) & 1;
            #pragma unroll
            for (int v = 0; v < 4; v++) {
                int u = tid + v * 128;
                int row = u >> 2, c8 = u & 3;
                *(uint4*)(sA[ns] + row * LDS_ + c8 * 8) = ra[v];
                *(uint4*)(sB[ns] + row * LDS_ + c8 * 8) = rb[v];
            }
        }
        __syncthreads();
    }

    // Epilogue: acc -> smem (f32, ld=132) -> coalesced scalar global stores
    float* sf = (float*)smem;   // 128*132*4 = 67584 bytes
    #pragma unroll
    for (int i = 0; i < 4; i++)
        #pragma unroll
        for (int j = 0; j < 4; j++)
            wmma::store_matrix_sync(sf + (size_t)(wm * 64 + i * 16) * 132 + wn * 64 + j * 16,
                                    acc[i][j], 132, wmma::mem_row_major);
    __syncthreads();

    const int colL = tid;            // 0..127
    const int colG = bn * 128 + colL;
    const float env = en[colG];
    const long long cbase = (long long)colOff + colG;
    #pragma unroll 4
    for (int r = 0; r < 128; r++) {
        int rg = bm * 128 + r;
        dist[(rowBase + rg) * (long long)KTOT + cbase] =
            qn[rg] + env - 2.0f * sf[(size_t)r * 132 + colL];
    }
}

// ---------------------------------------------------------------------------
// Approximate top-16 per query row. Register-resident strip, packed u64 keys
// (float_bits << 32 | idx): all distances > 0, so u64 min == (dist, idx)
// lexicographic min == jax's lower-index tie-break.
__global__ void __launch_bounds__(128)
topk_kernel(const float* __restrict__ out) {
    int q = blockIdx.x;
    int t = threadIdx.x;
    const float* row = out + OFF_DIST + (long long)q * KTOT + (q < NQ_CL ? 0 : KCB);

    unsigned long long key[32];
    #pragma unroll
    for (int j = 0; j < 32; j++) {
        float v = row[j * 128 + t];
        key[j] = ((unsigned long long)__float_as_uint(v) << 32) | (unsigned)(j * 128 + t);
    }
    unsigned long long lm = key[0];
    #pragma unroll
    for (int j = 1; j < 32; j++) lm = key[j] < lm ? key[j] : lm;

    __shared__ unsigned long long wmin[4];
    __shared__ unsigned long long win;

    for (int sel = 0; sel < NCAND; sel++) {
        unsigned long long m = lm;
        #pragma unroll
        for (int o = 16; o; o >>= 1) {
            unsigned long long other = __shfl_xor_sync(0xffffffffu, m, o);
            m = other < m ? other : m;
        }
        if ((t & 31) == 0) wmin[t >> 5] = m;
        __syncthreads();
        if (t == 0) {
            unsigned long long a = wmin[0] < wmin[1] ? wmin[0] : wmin[1];
            unsigned long long b = wmin[2] < wmin[3] ? wmin[2] : wmin[3];
            unsigned long long mm = a < b ? a : b;
            win = mm;
            g_cand[q * NCAND + sel] = (int)(mm & 0xffffffffu);
        }
        __syncthreads();
        unsigned widx = (unsigned)(win & 0xffffffffu);
        if ((widx & 127u) == (unsigned)t) {
            int jw = (int)(widx >> 7);
            #pragma unroll
            for (int j = 0; j < 32; j++) if (j == jw) key[j] = ~0ull;
            lm = key[0];
            #pragma unroll
            for (int j = 1; j < 32; j++) lm = key[j] < lm ? key[j] : lm;
        }
    }
}

// ---------------------------------------------------------------------------
// Exact fp32 rescore: one thread per (query, candidate), SEQUENTIAL fmaf over
// k = 0..767 in index order — bit-identical rounding to the fp32 GEMM whose
// selection matched jax exactly.
__global__ void __launch_bounds__(256)
rescore_pairs(const float* __restrict__ feats,
              const float* __restrict__ clsE, const float* __restrict__ ftE) {
    int g = blockIdx.x * 256 + threadIdx.x;
    if (g >= NQ_TOT * NCAND) return;
    int q = g / NCAND;
    int cand = g_cand[g];
    const float4* x = (const float4*)(feats + (size_t)q * CDIM);
    const float4* e = (const float4*)((q < NQ_CL ? clsE : ftE) + (size_t)cand * CDIM);
    float s = 0.f;
    #pragma unroll 8
    for (int i = 0; i < CDIM / 4; i++) {
        float4 a = x[i], b = e[i];
        s = fmaf(a.x, b.x, s);
        s = fmaf(a.y, b.y, s);
        s = fmaf(a.z, b.z, s);
        s = fmaf(a.w, b.w, s);
    }
    g_rd[g] = (g_qnorm[q] + g_enorm[(q < NQ_CL ? 0 : KCB) + cand]) - 2.f * s;
}

// Final top-3 from exact distances, lower-index tie-break; counts + idx output
__global__ void __launch_bounds__(256)
select_kernel(float* __restrict__ out) {
    int q = blockIdx.x * 256 + threadIdx.x;
    if (q >= NQ_TOT) return;
    float d[NCAND]; int id[NCAND]; bool used[NCAND];
    #pragma unroll
    for (int c = 0; c < NCAND; c++) {
        d[c] = g_rd[q * NCAND + c];
        id[c] = g_cand[q * NCAND + c];
        used[c] = false;
    }
    int base = (q < NQ_CL ? 0 : KCB);
    for (int sel = 0; sel < TOPK; sel++) {
        float bv = FLT_MAX; int bi = 0x7fffffff; int bw = 0;
        #pragma unroll
        for (int c = 0; c < NCAND; c++) {
            if (used[c]) continue;
            if (d[c] < bv || (d[c] == bv && id[c] < bi)) { bv = d[c]; bi = id[c]; bw = c; }
        }
        used[bw] = true;
        g_idx[q * TOPK + sel] = bi;
        out[OFF_IDX + q * TOPK + sel] = (float)(bi + base);
        atomicAdd(&g_cnt[base + bi], 1.0f);
    }
}

// Gather quantized = emb[idx] and accumulate commitment-loss sums
__global__ void __launch_bounds__(256)
gather_loss(const float* __restrict__ feats,
            const float* __restrict__ clsE, const float* __restrict__ ftE,
            float* __restrict__ outQ) {
    int g = blockIdx.x;
    int q = g / TOPK;
    int idx = g_idx[g];
    const float* x = feats + (size_t)q * CDIM;
    const float* e = (q < NQ_CL ? clsE : ftE) + (size_t)idx * CDIM;
    int t = threadIdx.x;
    float s = 0.f;
    #pragma unroll
    for (int i = t; i < CDIM; i += 256) {
        float ev = e[i];
        float d = ev - x[i];
        outQ[(size_t)g * CDIM + i] = ev;
        s += d * d;
    }
    __shared__ float red[256];
    red[t] = s; __syncthreads();
    for (int st = 128; st > 0; st >>= 1) { if (t < st) red[t] += red[t + st]; __syncthreads(); }
    if (t == 0) atomicAdd(&g_loss[q < NQ_CL ? 0 : 1], (double)red[0]);
}

// avg_probs, perplexities, loss scalar
__global__ void __launch_bounds__(1024)
finalize_kernel(float* __restrict__ out) {
    int b = blockIdx.x;
    int t = threadIdx.x;
    float N = (b == 0) ? (float)NQ_CL : (float)NQ_FT;
    float* avg = out + (b == 0 ? OFF_CLAVG : OFF_FTAVG);
    float ent = 0.f;
    for (int i = t; i < KCB; i += 1024) {
        float p = g_cnt[b * KCB + i] / N;
        avg[i] = p;
        ent += p * logf(p + 1e-10f);
    }
    __shared__ float red[1024];
    red[t] = ent; __syncthreads();
    for (int st = 512; st > 0; st >>= 1) { if (t < st) red[t] += red[t + st]; __syncthreads(); }
    if (t == 0) {
        out[b == 0 ? OFF_CLPERP : OFF_FTPERP] = expf(-red[0]);
        if (b == 0) {
            double mcl = g_loss[0] / ((double)NQ_CL * TOPK * CDIM);
            double mft = g_loss[1] / ((double)NQ_FT * TOPK * CDIM);
            out[OFF_LOSS] = (float)(0.25 * mft + 0.25 * mcl);
        }
    }
}

// ---------------------------------------------------------------------------
extern "C" void kernel_launch(void* const* d_in, const int* in_sizes, int n_in,
                              void* d_out, int out_size) {
    const float* feats = (const float*)d_in[0];   // (197,128,768)
    const float* clsE  = (const float*)d_in[1];   // (4096,768)
    const float* ftE   = (const float*)d_in[2];   // (4096,768)
    float* out = (float*)d_out;

    const int SMEM_GEMM = 67584;   // max(2*20480 staging, 128*132*4 epilogue)
    cudaFuncSetAttribute(gemm_wmma, cudaFuncAttributeMaxDynamicSharedMemorySize, SMEM_GEMM);

    init_kernel<<<(KTOT + 255) / 256, 256>>>();
    conv_norms_kernel<<<NQ_TOT + 2 * KCB, 256>>>(feats, clsE, ftE);

    {
        long long ntot = (long long)NQ_TOT * KCB;
        fill_kernel<<<(int)((ntot + 255) / 256), 256>>>(out);
    }

    __nv_bfloat16 *qbf, *cbf, *fbf;
    float *qnorm, *enorm;
    cudaGetSymbolAddress((void**)&qbf, g_qbf);
    cudaGetSymbolAddress((void**)&cbf, g_cbf);
    cudaGetSymbolAddress((void**)&fbf, g_fbf);
    cudaGetSymbolAddress((void**)&qnorm, g_qnorm);
    cudaGetSymbolAddress((void**)&enorm, g_enorm);

    // class: rows 0..127 -> dist cols [0,4096)
    gemm_wmma<<<dim3(1, 32), 128, SMEM_GEMM>>>(
        qbf, cbf, qnorm, enorm, out + OFF_DIST, 0LL, 0);
    // feat: rows 128..25215 -> dist cols [4096,8192)  (25088 = 196*128 exactly)
    gemm_wmma<<<dim3(196, 32), 128, SMEM_GEMM>>>(
        qbf + (size_t)NQ_CL * CDIM, fbf, qnorm + NQ_CL, enorm + KCB,
        out + OFF_DIST, (long long)NQ_CL, KCB);

    topk_kernel<<<NQ_TOT, 128>>>(out);
    rescore_pairs<<<(NQ_TOT * NCAND + 255) / 256, 256>>>(feats, clsE, ftE);
    select_kernel<<<(NQ_TOT + 255) / 256, 256>>>(out);
    gather_loss<<<NQ_TOT * TOPK, 256>>>(feats, clsE, ftE, out + OFF_QUANT);
    finalize_kernel<<<2, 1024>>>(out);
}

// round 12
// speedup vs baseline: 3.1253x; 1.2135x over previous
#include <cuda_runtime.h>
#include <cuda_bf16.h>
#include <mma.h>
#include <math.h>
#include <float.h>
#include <stdint.h>

using namespace nvcuda;

// Problem constants
#define NQ_TOT   25216
#define NQ_CL    128
#define NQ_FT    25088
#define CDIM     768
#define KCB      4096
#define KTOT     8192
#define TOPK     3
#define NCAND    16

// Output offsets (flattened tuple, all float32)
#define OFF_LOSS    0LL
#define OFF_QUANT   1LL
#define OFF_CLPERP  58097665LL
#define OFF_FTPERP  58097666LL
#define OFF_CLAVG   58097667LL
#define OFF_FTAVG   58101763LL
#define OFF_IDX     58105859LL
#define OFF_DIST    58181507LL   // not 16B-aligned: scalar access only in dist region

// ---------------------------------------------------------------------------
// Scratch (device globals — no allocation allowed)
__device__ __nv_bfloat16 g_qbf[(size_t)NQ_TOT * CDIM];
__device__ __nv_bfloat16 g_cbf[(size_t)KCB * CDIM];
__device__ __nv_bfloat16 g_fbf[(size_t)KCB * CDIM];
__device__ float  g_qnorm[NQ_TOT];
__device__ float  g_enorm[KTOT];          // [0..4095]=class, [4096..]=feat
__device__ int    g_cand[NQ_TOT * NCAND]; // approx top-16 raw indices
__device__ float  g_rd[NQ_TOT * NCAND];   // exact fp32 rescored distances
__device__ int    g_idx[NQ_TOT * TOPK];   // exact top-3 raw indices
__device__ float  g_cnt[KTOT];
__device__ double g_loss[2];

// ---------------------------------------------------------------------------
__device__ __forceinline__ void cp16(void* s, const void* g) {
    uint32_t sa = (uint32_t)__cvta_generic_to_shared(s);
    asm volatile("cp.async.cg.shared.global [%0], [%1], 16;" :: "r"(sa), "l"(g));
}
#define CP_COMMIT() asm volatile("cp.async.commit_group;" ::: "memory")
#define CP_WAIT1()  asm volatile("cp.async.wait_group 1;" ::: "memory")

// ---------------------------------------------------------------------------
__global__ void init_kernel() {
    int t = blockIdx.x * blockDim.x + threadIdx.x;
    if (t < KTOT) g_cnt[t] = 0.0f;
    if (t < 2) g_loss[t] = 0.0;
}

// Fused: fp32 -> bf16 conversion AND row L2-norms (one read pass).
__global__ void conv_norms_kernel(const float* __restrict__ feats,
                                  const float* __restrict__ clsE,
                                  const float* __restrict__ ftE) {
    int row = blockIdx.x;
    const float* src; float* ndst; __nv_bfloat16* bdst;
    if (row < NQ_TOT) {
        src = feats + (size_t)row * CDIM; ndst = g_qnorm + row; bdst = g_qbf + (size_t)row * CDIM;
    } else if (row < NQ_TOT + KCB) {
        int r = row - NQ_TOT;
        src = clsE + (size_t)r * CDIM; ndst = g_enorm + r; bdst = g_cbf + (size_t)r * CDIM;
    } else {
        int r = row - NQ_TOT - KCB;
        src = ftE + (size_t)r * CDIM; ndst = g_enorm + KCB + r; bdst = g_fbf + (size_t)r * CDIM;
    }
    int t = threadIdx.x;  // 256
    float s = 0.f;
    #pragma unroll
    for (int i = t; i < CDIM; i += 256) {
        float v = src[i];
        bdst[i] = __float2bfloat16(v);
        s = fmaf(v, v, s);
    }
    __shared__ float red[256];
    red[t] = s; __syncthreads();
    for (int st = 128; st > 0; st >>= 1) { if (t < st) red[t] += red[t + st]; __syncthreads(); }
    if (t == 0) *ndst = red[0];
}

// ---------------------------------------------------------------------------
// bf16 WMMA GEMM + distance epilogue + fused FLT_MAX padding fill.
// grid (197, 32): bm==0 -> class tile (A rows 0..127, B = class codebook),
// bm>=1 -> feat tile (A rows bm*128.., B = feat codebook).
// CTA tile 128x128, 4 warps (64x64 warp tile), BK=32, cp.async 3-stage.
#define BK     32
#define LDS_   40     // bf16 row stride (80B, 16B-aligned)
#define NCHK   (CDIM / BK)   // 24
#define STAGEB 20480  // bytes per stage (A 10240 + B 10240)

__global__ void __launch_bounds__(128, 2)
gemm_wmma(const __nv_bfloat16* __restrict__ Q,
          const __nv_bfloat16* __restrict__ Ccls,
          const __nv_bfloat16* __restrict__ Cft,
          const float* __restrict__ qn, const float* __restrict__ en,
          float* __restrict__ dist /* out + OFF_DIST */)
{
    extern __shared__ char smem[];
    const int tid = threadIdx.x;
    const int wid = tid >> 5;
    const int bm = blockIdx.x, bn = blockIdx.y;
    const int wm = wid & 1;
    const int wn = wid >> 1;

    const __nv_bfloat16* Abase = Q + (size_t)bm * 128 * CDIM;
    const __nv_bfloat16* Bbase = ((bm == 0) ? Ccls : Cft) + (size_t)bn * 128 * CDIM;
    const int colOff = (bm == 0) ? 0 : KCB;

    // stage layout: sA = smem + s*STAGEB, sB = sA + 10240
    // load map: u = tid + v*128 -> row = u>>2, c8 = u&3 (4 uint4 each for A,B)
    int lrow[4], lc8[4];
    #pragma unroll
    for (int v = 0; v < 4; v++) { int u = tid + v * 128; lrow[v] = u >> 2; lc8[v] = u & 3; }

    wmma::fragment<wmma::accumulator, 16, 16, 16, float> acc[4][4];
    #pragma unroll
    for (int i = 0; i < 4; i++)
        #pragma unroll
        for (int j = 0; j < 4; j++) wmma::fill_fragment(acc[i][j], 0.0f);

    // prefetch stages 0,1
    #pragma unroll
    for (int p = 0; p < 2; p++) {
        char* sA = smem + p * STAGEB;
        char* sB = sA + 10240;
        const int kk = p * BK;
        #pragma unroll
        for (int v = 0; v < 4; v++) {
            cp16(sA + (lrow[v] * LDS_ + lc8[v] * 8) * 2, Abase + (size_t)lrow[v] * CDIM + kk + lc8[v] * 8);
            cp16(sB + (lrow[v] * LDS_ + lc8[v] * 8) * 2, Bbase + (size_t)lrow[v] * CDIM + kk + lc8[v] * 8);
        }
        CP_COMMIT();
    }

    for (int c = 0; c < NCHK; c++) {
        const int s = c % 3;
        CP_WAIT1();            // stage c's group complete (<=1 group pending)
        __syncthreads();       // also guards reuse of slot (c-1)%3 below

        __nv_bfloat16* sA = (__nv_bfloat16*)(smem + s * STAGEB);
        __nv_bfloat16* sB = (__nv_bfloat16*)(smem + s * STAGEB + 10240);

        #pragma unroll
        for (int kk = 0; kk < BK / 16; kk++) {
            wmma::fragment<wmma::matrix_a, 16, 16, 16, __nv_bfloat16, wmma::row_major> af[4];
            wmma::fragment<wmma::matrix_b, 16, 16, 16, __nv_bfloat16, wmma::col_major> bf[4];
            #pragma unroll
            for (int i = 0; i < 4; i++)
                wmma::load_matrix_sync(af[i], sA + (wm * 64 + i * 16) * LDS_ + kk * 16, LDS_);
            #pragma unroll
            for (int j = 0; j < 4; j++)
                wmma::load_matrix_sync(bf[j], sB + (wn * 64 + j * 16) * LDS_ + kk * 16, LDS_);
            #pragma unroll
            for (int i = 0; i < 4; i++)
                #pragma unroll
                for (int j = 0; j < 4; j++)
                    wmma::mma_sync(acc[i][j], af[i], bf[j], acc[i][j]);
        }

        if (c + 2 < NCHK) {
            const int ns = (c + 2) % 3;
            char* nA = smem + ns * STAGEB;
            char* nB = nA + 10240;
            const int kk = (c + 2) * BK;
            #pragma unroll
            for (int v = 0; v < 4; v++) {
                cp16(nA + (lrow[v] * LDS_ + lc8[v] * 8) * 2, Abase + (size_t)lrow[v] * CDIM + kk + lc8[v] * 8);
                cp16(nB + (lrow[v] * LDS_ + lc8[v] * 8) * 2, Bbase + (size_t)lrow[v] * CDIM + kk + lc8[v] * 8);
            }
        }
        CP_COMMIT();           // one group per iteration keeps the count model
    }
    __syncthreads();

    // Epilogue: acc -> smem (f32, ld=132) -> coalesced scalar stores + padding
    float* sf = (float*)smem;   // 128*132*4 = 67584 bytes
    #pragma unroll
    for (int i = 0; i < 4; i++)
        #pragma unroll
        for (int j = 0; j < 4; j++)
            wmma::store_matrix_sync(sf + (size_t)(wm * 64 + i * 16) * 132 + wn * 64 + j * 16,
                                    acc[i][j], 132, wmma::mem_row_major);
    __syncthreads();

    const int colL = tid;             // 0..127
    const int colG = bn * 128 + colL; // codebook-local column
    const float env = en[colOff + colG];
    const long long cReal = (long long)(colOff + colG);
    const long long cPad  = (long long)((colOff ^ KCB) + colG);
    #pragma unroll 4
    for (int r = 0; r < 128; r++) {
        const long long rbase = (long long)(bm * 128 + r) * KTOT;
        dist[rbase + cReal] = qn[bm * 128 + r] + env - 2.0f * sf[(size_t)r * 132 + colL];
        dist[rbase + cPad]  = FLT_MAX;
    }
}

// ---------------------------------------------------------------------------
// Approximate top-16 per query row. Register-resident strip, packed u64 keys
// (float_bits << 32 | idx): all distances > 0, so u64 min == lexicographic min
// == jax's lower-index tie-break.
__global__ void __launch_bounds__(128)
topk_kernel(const float* __restrict__ out) {
    int q = blockIdx.x;
    int t = threadIdx.x;
    const float* row = out + OFF_DIST + (long long)q * KTOT + (q < NQ_CL ? 0 : KCB);

    unsigned long long key[32];
    #pragma unroll
    for (int j = 0; j < 32; j++) {
        float v = row[j * 128 + t];
        key[j] = ((unsigned long long)__float_as_uint(v) << 32) | (unsigned)(j * 128 + t);
    }
    unsigned long long lm = key[0];
    #pragma unroll
    for (int j = 1; j < 32; j++) lm = key[j] < lm ? key[j] : lm;

    __shared__ unsigned long long wmin[4];
    __shared__ unsigned long long win;

    for (int sel = 0; sel < NCAND; sel++) {
        unsigned long long m = lm;
        #pragma unroll
        for (int o = 16; o; o >>= 1) {
            unsigned long long other = __shfl_xor_sync(0xffffffffu, m, o);
            m = other < m ? other : m;
        }
        if ((t & 31) == 0) wmin[t >> 5] = m;
        __syncthreads();
        if (t == 0) {
            unsigned long long a = wmin[0] < wmin[1] ? wmin[0] : wmin[1];
            unsigned long long b = wmin[2] < wmin[3] ? wmin[2] : wmin[3];
            unsigned long long mm = a < b ? a : b;
            win = mm;
            g_cand[q * NCAND + sel] = (int)(mm & 0xffffffffu);
        }
        __syncthreads();
        unsigned widx = (unsigned)(win & 0xffffffffu);
        if ((widx & 127u) == (unsigned)t) {
            int jw = (int)(widx >> 7);
            #pragma unroll
            for (int j = 0; j < 32; j++) if (j == jw) key[j] = ~0ull;
            lm = key[0];
            #pragma unroll
            for (int j = 1; j < 32; j++) lm = key[j] < lm ? key[j] : lm;
        }
    }
}

// ---------------------------------------------------------------------------
// Exact fp32 rescore: sequential fmaf over k in index order — bit-identical
// to the fp32 GEMM ordering that matched jax exactly.
__global__ void __launch_bounds__(256)
rescore_pairs(const float* __restrict__ feats,
              const float* __restrict__ clsE, const float* __restrict__ ftE) {
    int g = blockIdx.x * 256 + threadIdx.x;
    if (g >= NQ_TOT * NCAND) return;
    int q = g / NCAND;
    int cand = g_cand[g];
    const float4* x = (const float4*)(feats + (size_t)q * CDIM);
    const float4* e = (const float4*)((q < NQ_CL ? clsE : ftE) + (size_t)cand * CDIM);
    float s = 0.f;
    #pragma unroll 8
    for (int i = 0; i < CDIM / 4; i++) {
        float4 a = x[i], b = e[i];
        s = fmaf(a.x, b.x, s);
        s = fmaf(a.y, b.y, s);
        s = fmaf(a.z, b.z, s);
        s = fmaf(a.w, b.w, s);
    }
    g_rd[g] = (g_qnorm[q] + g_enorm[(q < NQ_CL ? 0 : KCB) + cand]) - 2.f * s;
}

// Final top-3 from exact distances, lower-index tie-break; counts + idx output
__global__ void __launch_bounds__(256)
select_kernel(float* __restrict__ out) {
    int q = blockIdx.x * 256 + threadIdx.x;
    if (q >= NQ_TOT) return;
    float d[NCAND]; int id[NCAND]; bool used[NCAND];
    #pragma unroll
    for (int c = 0; c < NCAND; c++) {
        d[c] = g_rd[q * NCAND + c];
        id[c] = g_cand[q * NCAND + c];
        used[c] = false;
    }
    int base = (q < NQ_CL ? 0 : KCB);
    for (int sel = 0; sel < TOPK; sel++) {
        float bv = FLT_MAX; int bi = 0x7fffffff; int bw = 0;
        #pragma unroll
        for (int c = 0; c < NCAND; c++) {
            if (used[c]) continue;
            if (d[c] < bv || (d[c] == bv && id[c] < bi)) { bv = d[c]; bi = id[c]; bw = c; }
        }
        used[bw] = true;
        g_idx[q * TOPK + sel] = bi;
        out[OFF_IDX + q * TOPK + sel] = (float)(bi + base);
        atomicAdd(&g_cnt[base + bi], 1.0f);
    }
}

// Gather quantized = emb[idx] and accumulate commitment-loss sums
__global__ void __launch_bounds__(256)
gather_loss(const float* __restrict__ feats,
            const float* __restrict__ clsE, const float* __restrict__ ftE,
            float* __restrict__ outQ) {
    int g = blockIdx.x;
    int q = g / TOPK;
    int idx = g_idx[g];
    const float* x = feats + (size_t)q * CDIM;
    const float* e = (q < NQ_CL ? clsE : ftE) + (size_t)idx * CDIM;
    int t = threadIdx.x;
    float s = 0.f;
    #pragma unroll
    for (int i = t; i < CDIM; i += 256) {
        float ev = e[i];
        float d = ev - x[i];
        outQ[(size_t)g * CDIM + i] = ev;
        s += d * d;
    }
    __shared__ float red[256];
    red[t] = s; __syncthreads();
    for (int st = 128; st > 0; st >>= 1) { if (t < st) red[t] += red[t + st]; __syncthreads(); }
    if (t == 0) atomicAdd(&g_loss[q < NQ_CL ? 0 : 1], (double)red[0]);
}

// avg_probs, perplexities, loss scalar
__global__ void __launch_bounds__(1024)
finalize_kernel(float* __restrict__ out) {
    int b = blockIdx.x;
    int t = threadIdx.x;
    float N = (b == 0) ? (float)NQ_CL : (float)NQ_FT;
    float* avg = out + (b == 0 ? OFF_CLAVG : OFF_FTAVG);
    float ent = 0.f;
    for (int i = t; i < KCB; i += 1024) {
        float p = g_cnt[b * KCB + i] / N;
        avg[i] = p;
        ent += p * logf(p + 1e-10f);
    }
    __shared__ float red[1024];
    red[t] = ent; __syncthreads();
    for (int st = 512; st > 0; st >>= 1) { if (t < st) red[t] += red[t + st]; __syncthreads(); }
    if (t == 0) {
        out[b == 0 ? OFF_CLPERP : OFF_FTPERP] = expf(-red[0]);
        if (b == 0) {
            double mcl = g_loss[0] / ((double)NQ_CL * TOPK * CDIM);
            double mft = g_loss[1] / ((double)NQ_FT * TOPK * CDIM);
            out[OFF_LOSS] = (float)(0.25 * mft + 0.25 * mcl);
        }
    }
}

// ---------------------------------------------------------------------------
extern "C" void kernel_launch(void* const* d_in, const int* in_sizes, int n_in,
                              void* d_out, int out_size) {
    const float* feats = (const float*)d_in[0];   // (197,128,768)
    const float* clsE  = (const float*)d_in[1];   // (4096,768)
    const float* ftE   = (const float*)d_in[2];   // (4096,768)
    float* out = (float*)d_out;

    const int SMEM_GEMM = 67584;   // max(3*20480 staging, 128*132*4 epilogue)
    cudaFuncSetAttribute(gemm_wmma, cudaFuncAttributeMaxDynamicSharedMemorySize, SMEM_GEMM);

    init_kernel<<<(KTOT + 255) / 256, 256>>>();
    conv_norms_kernel<<<NQ_TOT + 2 * KCB, 256>>>(feats, clsE, ftE);

    __nv_bfloat16 *qbf, *cbf, *fbf;
    float *qnorm, *enorm;
    cudaGetSymbolAddress((void**)&qbf, g_qbf);
    cudaGetSymbolAddress((void**)&cbf, g_cbf);
    cudaGetSymbolAddress((void**)&fbf, g_fbf);
    cudaGetSymbolAddress((void**)&qnorm, g_qnorm);
    cudaGetSymbolAddress((void**)&enorm, g_enorm);

    // Unified GEMM: bm 0 = class tile, bm 1..196 = feat tiles.
    // Epilogue also writes the FLT_MAX padding half (fill kernel eliminated).
    gemm_wmma<<<dim3(197, 32), 128, SMEM_GEMM>>>(
        qbf, cbf, fbf, qnorm, enorm, out + OFF_DIST);

    topk_kernel<<<NQ_TOT, 128>>>(out);
    rescore_pairs<<<(NQ_TOT * NCAND + 255) / 256, 256>>>(feats, clsE, ftE);
    select_kernel<<<(NQ_TOT + 255) / 256, 256>>>(out);
    gather_loss<<<NQ_TOT * TOPK, 256>>>(feats, clsE, ftE, out + OFF_QUANT);
    finalize_kernel<<<2, 1024>>>(out);
}

// round 13
// speedup vs baseline: 3.8104x; 1.2192x over previous
#include <cuda_runtime.h>
#include <cuda_bf16.h>
#include <mma.h>
#include <math.h>
#include <float.h>
#include <stdint.h>

using namespace nvcuda;

// Problem constants
#define NQ_TOT   25216
#define NQ_CL    128
#define NQ_FT    25088
#define CDIM     768
#define KCB      4096
#define KTOT     8192
#define TOPK     3
#define NCAND    16

// Output offsets (flattened tuple, all float32)
#define OFF_LOSS    0LL
#define OFF_QUANT   1LL
#define OFF_CLPERP  58097665LL
#define OFF_FTPERP  58097666LL
#define OFF_CLAVG   58097667LL
#define OFF_FTAVG   58101763LL
#define OFF_IDX     58105859LL
#define OFF_DIST    58181507LL   // not 16B-aligned: scalar access only in dist region

// ---------------------------------------------------------------------------
// Scratch (device globals — no allocation allowed)
__device__ __nv_bfloat16 g_qbf[(size_t)NQ_TOT * CDIM];
__device__ __nv_bfloat16 g_cbf[(size_t)KCB * CDIM];
__device__ __nv_bfloat16 g_fbf[(size_t)KCB * CDIM];
__device__ float  g_qnorm[NQ_TOT];
__device__ float  g_enorm[KTOT];          // [0..4095]=class, [4096..]=feat
__device__ int    g_cand[NQ_TOT * NCAND]; // approx top-16 raw indices
__device__ float  g_rd[NQ_TOT * NCAND];   // exact fp32 rescored distances
__device__ int    g_idx[NQ_TOT * TOPK];   // exact top-3 raw indices
__device__ float  g_cnt[KTOT];
__device__ double g_loss[2];

// ---------------------------------------------------------------------------
__device__ __forceinline__ void cp16(void* s, const void* g) {
    uint32_t sa = (uint32_t)__cvta_generic_to_shared(s);
    asm volatile("cp.async.cg.shared.global [%0], [%1], 16;" :: "r"(sa), "l"(g));
}
#define CP_COMMIT() asm volatile("cp.async.commit_group;" ::: "memory")
#define CP_WAIT1()  asm volatile("cp.async.wait_group 1;" ::: "memory")

// ---------------------------------------------------------------------------
__global__ void init_kernel() {
    int t = blockIdx.x * blockDim.x + threadIdx.x;
    if (t < KTOT) g_cnt[t] = 0.0f;
    if (t < 2) g_loss[t] = 0.0;
}

// Fused: fp32 -> bf16 conversion AND row L2-norms (one read pass).
__global__ void conv_norms_kernel(const float* __restrict__ feats,
                                  const float* __restrict__ clsE,
                                  const float* __restrict__ ftE) {
    int row = blockIdx.x;
    const float* src; float* ndst; __nv_bfloat16* bdst;
    if (row < NQ_TOT) {
        src = feats + (size_t)row * CDIM; ndst = g_qnorm + row; bdst = g_qbf + (size_t)row * CDIM;
    } else if (row < NQ_TOT + KCB) {
        int r = row - NQ_TOT;
        src = clsE + (size_t)r * CDIM; ndst = g_enorm + r; bdst = g_cbf + (size_t)r * CDIM;
    } else {
        int r = row - NQ_TOT - KCB;
        src = ftE + (size_t)r * CDIM; ndst = g_enorm + KCB + r; bdst = g_fbf + (size_t)r * CDIM;
    }
    int t = threadIdx.x;  // 256
    float s = 0.f;
    #pragma unroll
    for (int i = t; i < CDIM; i += 256) {
        float v = src[i];
        bdst[i] = __float2bfloat16(v);
        s = fmaf(v, v, s);
    }
    __shared__ float red[256];
    red[t] = s; __syncthreads();
    for (int st = 128; st > 0; st >>= 1) { if (t < st) red[t] += red[t + st]; __syncthreads(); }
    if (t == 0) *ndst = red[0];
}

// ---------------------------------------------------------------------------
// bf16 WMMA GEMM + distance epilogue + fused FLT_MAX padding fill.
// grid (197, 32): bm==0 -> class tile, bm>=1 -> feat tile.
// CTA tile 128x128, 4 warps (64x64 warp tile), BK=32, cp.async 3-stage.
#define BK     32
#define LDS_   40     // bf16 row stride (80B, 16B-aligned)
#define NCHK   (CDIM / BK)   // 24
#define STAGEB 20480  // bytes per stage (A 10240 + B 10240)

__global__ void __launch_bounds__(128, 2)
gemm_wmma(const __nv_bfloat16* __restrict__ Q,
          const __nv_bfloat16* __restrict__ Ccls,
          const __nv_bfloat16* __restrict__ Cft,
          const float* __restrict__ qn, const float* __restrict__ en,
          float* __restrict__ dist /* out + OFF_DIST */)
{
    extern __shared__ char smem[];
    const int tid = threadIdx.x;
    const int wid = tid >> 5;
    const int bm = blockIdx.x, bn = blockIdx.y;
    const int wm = wid & 1;
    const int wn = wid >> 1;

    const __nv_bfloat16* Abase = Q + (size_t)bm * 128 * CDIM;
    const __nv_bfloat16* Bbase = ((bm == 0) ? Ccls : Cft) + (size_t)bn * 128 * CDIM;
    const int colOff = (bm == 0) ? 0 : KCB;

    int lrow[4], lc8[4];
    #pragma unroll
    for (int v = 0; v < 4; v++) { int u = tid + v * 128; lrow[v] = u >> 2; lc8[v] = u & 3; }

    wmma::fragment<wmma::accumulator, 16, 16, 16, float> acc[4][4];
    #pragma unroll
    for (int i = 0; i < 4; i++)
        #pragma unroll
        for (int j = 0; j < 4; j++) wmma::fill_fragment(acc[i][j], 0.0f);

    #pragma unroll
    for (int p = 0; p < 2; p++) {
        char* sA = smem + p * STAGEB;
        char* sB = sA + 10240;
        const int kk = p * BK;
        #pragma unroll
        for (int v = 0; v < 4; v++) {
            cp16(sA + (lrow[v] * LDS_ + lc8[v] * 8) * 2, Abase + (size_t)lrow[v] * CDIM + kk + lc8[v] * 8);
            cp16(sB + (lrow[v] * LDS_ + lc8[v] * 8) * 2, Bbase + (size_t)lrow[v] * CDIM + kk + lc8[v] * 8);
        }
        CP_COMMIT();
    }

    for (int c = 0; c < NCHK; c++) {
        const int s = c % 3;
        CP_WAIT1();
        __syncthreads();

        __nv_bfloat16* sA = (__nv_bfloat16*)(smem + s * STAGEB);
        __nv_bfloat16* sB = (__nv_bfloat16*)(smem + s * STAGEB + 10240);

        #pragma unroll
        for (int kk = 0; kk < BK / 16; kk++) {
            wmma::fragment<wmma::matrix_a, 16, 16, 16, __nv_bfloat16, wmma::row_major> af[4];
            wmma::fragment<wmma::matrix_b, 16, 16, 16, __nv_bfloat16, wmma::col_major> bf[4];
            #pragma unroll
            for (int i = 0; i < 4; i++)
                wmma::load_matrix_sync(af[i], sA + (wm * 64 + i * 16) * LDS_ + kk * 16, LDS_);
            #pragma unroll
            for (int j = 0; j < 4; j++)
                wmma::load_matrix_sync(bf[j], sB + (wn * 64 + j * 16) * LDS_ + kk * 16, LDS_);
            #pragma unroll
            for (int i = 0; i < 4; i++)
                #pragma unroll
                for (int j = 0; j < 4; j++)
                    wmma::mma_sync(acc[i][j], af[i], bf[j], acc[i][j]);
        }

        if (c + 2 < NCHK) {
            const int ns = (c + 2) % 3;
            char* nA = smem + ns * STAGEB;
            char* nB = nA + 10240;
            const int kk = (c + 2) * BK;
            #pragma unroll
            for (int v = 0; v < 4; v++) {
                cp16(nA + (lrow[v] * LDS_ + lc8[v] * 8) * 2, Abase + (size_t)lrow[v] * CDIM + kk + lc8[v] * 8);
                cp16(nB + (lrow[v] * LDS_ + lc8[v] * 8) * 2, Bbase + (size_t)lrow[v] * CDIM + kk + lc8[v] * 8);
            }
        }
        CP_COMMIT();
    }
    __syncthreads();

    // Epilogue: acc -> smem (f32, ld=132) -> coalesced scalar stores + padding
    float* sf = (float*)smem;   // 128*132*4 = 67584 bytes
    #pragma unroll
    for (int i = 0; i < 4; i++)
        #pragma unroll
        for (int j = 0; j < 4; j++)
            wmma::store_matrix_sync(sf + (size_t)(wm * 64 + i * 16) * 132 + wn * 64 + j * 16,
                                    acc[i][j], 132, wmma::mem_row_major);
    __syncthreads();

    const int colL = tid;
    const int colG = bn * 128 + colL;
    const float env = en[colOff + colG];
    const long long cReal = (long long)(colOff + colG);
    const long long cPad  = (long long)((colOff ^ KCB) + colG);
    #pragma unroll 4
    for (int r = 0; r < 128; r++) {
        const long long rbase = (long long)(bm * 128 + r) * KTOT;
        dist[rbase + cReal] = qn[bm * 128 + r] + env - 2.0f * sf[(size_t)r * 132 + colL];
        dist[rbase + cPad]  = FLT_MAX;
    }
}

// ---------------------------------------------------------------------------
// Approximate top-16 per query row, u32 packed keys.
// key = (dist_bits & 0xFFFFF000) | idx. Distances are positive fp32, so bit
// pattern order == numeric order; truncating 12 mantissa bits adds <=2^-11
// rel noise (harmless: candidates are exact-rescored). u32 min gives
// lower-index tie-break like jax. Owner-only removal per round.
__global__ void __launch_bounds__(128)
topk_kernel(const float* __restrict__ out) {
    int q = blockIdx.x;
    int t = threadIdx.x;
    const float* row = out + OFF_DIST + (long long)q * KTOT + (q < NQ_CL ? 0 : KCB);

    unsigned key[32];
    #pragma unroll
    for (int j = 0; j < 32; j++) {
        unsigned vb = __float_as_uint(row[j * 128 + t]);
        key[j] = (vb & 0xFFFFF000u) | (unsigned)(j * 128 + t);
    }
    unsigned lm = key[0];
    #pragma unroll
    for (int j = 1; j < 32; j++) lm = min(lm, key[j]);

    __shared__ unsigned wmin[4];
    __shared__ unsigned win;

    for (int sel = 0; sel < NCAND; sel++) {
        unsigned m = lm;
        #pragma unroll
        for (int o = 16; o; o >>= 1)
            m = min(m, __shfl_xor_sync(0xffffffffu, m, o));
        if ((t & 31) == 0) wmin[t >> 5] = m;
        __syncthreads();
        if (t == 0) {
            unsigned mm = min(min(wmin[0], wmin[1]), min(wmin[2], wmin[3]));
            win = mm;
            g_cand[q * NCAND + sel] = (int)(mm & 0xFFFu);
        }
        __syncthreads();
        unsigned widx = win & 0xFFFu;
        if ((widx & 127u) == (unsigned)t) {
            key[widx >> 7] = 0xFFFFFFFFu;
            lm = key[0];
            #pragma unroll
            for (int j = 1; j < 32; j++) lm = min(lm, key[j]);
        }
    }
}

// ---------------------------------------------------------------------------
// Exact fp32 rescore: sequential fmaf over k in index order — bit-identical
// to the fp32 GEMM ordering that matched jax exactly.
__global__ void __launch_bounds__(256)
rescore_pairs(const float* __restrict__ feats,
              const float* __restrict__ clsE, const float* __restrict__ ftE) {
    int g = blockIdx.x * 256 + threadIdx.x;
    if (g >= NQ_TOT * NCAND) return;
    int q = g / NCAND;
    int cand = g_cand[g];
    const float4* x = (const float4*)(feats + (size_t)q * CDIM);
    const float4* e = (const float4*)((q < NQ_CL ? clsE : ftE) + (size_t)cand * CDIM);
    float s = 0.f;
    #pragma unroll 8
    for (int i = 0; i < CDIM / 4; i++) {
        float4 a = x[i], b = e[i];
        s = fmaf(a.x, b.x, s);
        s = fmaf(a.y, b.y, s);
        s = fmaf(a.z, b.z, s);
        s = fmaf(a.w, b.w, s);
    }
    g_rd[g] = (g_qnorm[q] + g_enorm[(q < NQ_CL ? 0 : KCB) + cand]) - 2.f * s;
}

// Final top-3 from exact distances, lower-index tie-break; counts + idx output
__global__ void __launch_bounds__(256)
select_kernel(float* __restrict__ out) {
    int q = blockIdx.x * 256 + threadIdx.x;
    if (q >= NQ_TOT) return;
    float d[NCAND]; int id[NCAND]; bool used[NCAND];
    #pragma unroll
    for (int c = 0; c < NCAND; c++) {
        d[c] = g_rd[q * NCAND + c];
        id[c] = g_cand[q * NCAND + c];
        used[c] = false;
    }
    int base = (q < NQ_CL ? 0 : KCB);
    for (int sel = 0; sel < TOPK; sel++) {
        float bv = FLT_MAX; int bi = 0x7fffffff; int bw = 0;
        #pragma unroll
        for (int c = 0; c < NCAND; c++) {
            if (used[c]) continue;
            if (d[c] < bv || (d[c] == bv && id[c] < bi)) { bv = d[c]; bi = id[c]; bw = c; }
        }
        used[bw] = true;
        g_idx[q * TOPK + sel] = bi;
        out[OFF_IDX + q * TOPK + sel] = (float)(bi + base);
        atomicAdd(&g_cnt[base + bi], 1.0f);
    }
}

// Gather quantized = emb[idx] and accumulate commitment-loss sums
__global__ void __launch_bounds__(256)
gather_loss(const float* __restrict__ feats,
            const float* __restrict__ clsE, const float* __restrict__ ftE,
            float* __restrict__ outQ) {
    int g = blockIdx.x;
    int q = g / TOPK;
    int idx = g_idx[g];
    const float* x = feats + (size_t)q * CDIM;
    const float* e = (q < NQ_CL ? clsE : ftE) + (size_t)idx * CDIM;
    int t = threadIdx.x;
    float s = 0.f;
    #pragma unroll
    for (int i = t; i < CDIM; i += 256) {
        float ev = e[i];
        float d = ev - x[i];
        outQ[(size_t)g * CDIM + i] = ev;
        s += d * d;
    }
    __shared__ float red[256];
    red[t] = s; __syncthreads();
    for (int st = 128; st > 0; st >>= 1) { if (t < st) red[t] += red[t + st]; __syncthreads(); }
    if (t == 0) atomicAdd(&g_loss[q < NQ_CL ? 0 : 1], (double)red[0]);
}

// avg_probs, perplexities, loss scalar
__global__ void __launch_bounds__(1024)
finalize_kernel(float* __restrict__ out) {
    int b = blockIdx.x;
    int t = threadIdx.x;
    float N = (b == 0) ? (float)NQ_CL : (float)NQ_FT;
    float* avg = out + (b == 0 ? OFF_CLAVG : OFF_FTAVG);
    float ent = 0.f;
    for (int i = t; i < KCB; i += 1024) {
        float p = g_cnt[b * KCB + i] / N;
        avg[i] = p;
        ent += p * logf(p + 1e-10f);
    }
    __shared__ float red[1024];
    red[t] = ent; __syncthreads();
    for (int st = 512; st > 0; st >>= 1) { if (t < st) red[t] += red[t + st]; __syncthreads(); }
    if (t == 0) {
        out[b == 0 ? OFF_CLPERP : OFF_FTPERP] = expf(-red[0]);
        if (b == 0) {
            double mcl = g_loss[0] / ((double)NQ_CL * TOPK * CDIM);
            double mft = g_loss[1] / ((double)NQ_FT * TOPK * CDIM);
            out[OFF_LOSS] = (float)(0.25 * mft + 0.25 * mcl);
        }
    }
}

// ---------------------------------------------------------------------------
extern "C" void kernel_launch(void* const* d_in, const int* in_sizes, int n_in,
                              void* d_out, int out_size) {
    const float* feats = (const float*)d_in[0];   // (197,128,768)
    const float* clsE  = (const float*)d_in[1];   // (4096,768)
    const float* ftE   = (const float*)d_in[2];   // (4096,768)
    float* out = (float*)d_out;

    const int SMEM_GEMM = 67584;   // max(3*20480 staging, 128*132*4 epilogue)
    cudaFuncSetAttribute(gemm_wmma, cudaFuncAttributeMaxDynamicSharedMemorySize, SMEM_GEMM);

    init_kernel<<<(KTOT + 255) / 256, 256>>>();
    conv_norms_kernel<<<NQ_TOT + 2 * KCB, 256>>>(feats, clsE, ftE);

    __nv_bfloat16 *qbf, *cbf, *fbf;
    float *qnorm, *enorm;
    cudaGetSymbolAddress((void**)&qbf, g_qbf);
    cudaGetSymbolAddress((void**)&cbf, g_cbf);
    cudaGetSymbolAddress((void**)&fbf, g_fbf);
    cudaGetSymbolAddress((void**)&qnorm, g_qnorm);
    cudaGetSymbolAddress((void**)&enorm, g_enorm);

    // Unified GEMM: bm 0 = class tile, bm 1..196 = feat tiles.
    gemm_wmma<<<dim3(197, 32), 128, SMEM_GEMM>>>(
        qbf, cbf, fbf, qnorm, enorm, out + OFF_DIST);

    topk_kernel<<<NQ_TOT, 128>>>(out);
    rescore_pairs<<<(NQ_TOT * NCAND + 255) / 256, 256>>>(feats, clsE, ftE);
    select_kernel<<<(NQ_TOT + 255) / 256, 256>>>(out);
    gather_loss<<<NQ_TOT * TOPK, 256>>>(feats, clsE, ftE, out + OFF_QUANT);
    finalize_kernel<<<2, 1024>>>(out);
}